// round 4
// baseline (speedup 1.0000x reference)
#include <cuda_runtime.h>
#include <cuda_bf16.h>

#define T_TOKENS 16384
#define NEXP     64
#define KDIM     4096
#define BT       64      // tokens per block
#define KT       32      // K tile
#define THREADS  256

typedef unsigned long long u64;

__device__ __forceinline__ u64 ffma2(u64 a, u64 b, u64 c) {
    u64 d;
    asm("fma.rn.f32x2 %0, %1, %2, %3;" : "=l"(d) : "l"(a), "l"(b), "l"(c));
    return d;
}
__device__ __forceinline__ u64 packdup(float v) {
    u64 d;
    asm("mov.b64 %0, {%1, %1};" : "=l"(d) : "f"(v));
    return d;
}
__device__ __forceinline__ void unpack2(u64 v, float &lo, float &hi) {
    asm("mov.b64 {%0, %1}, %2;" : "=f"(lo), "=f"(hi) : "l"(v));
}

__global__ __launch_bounds__(THREADS)
void router_kernel(const float* __restrict__ x,
                   const float* __restrict__ W,
                   float* __restrict__ out)
{
    __shared__ union {
        struct {
            float xs[KT][BT + 2];   // transposed: [k][token], pad 66 (8B-align ok, spreads banks)
            float ws[KT][NEXP + 4]; // transposed: [k][expert], pad 68 (16B-align for float4)
        } g;
        float lg[BT][NEXP + 1];     // logits for epilogue (reuses same smem)
    } sm;

    const int tid = threadIdx.x;
    const int t0  = blockIdx.x * BT;

    const int tm = (tid >> 4) << 2;  // token micro-tile base (0..60), even
    const int tn = (tid & 15) << 2;  // expert micro-tile base (0..60), mult of 4

    // acc[p][j]: packed pair of tokens (tm+2p, tm+2p+1) for expert tn+j
    u64 acc[2][4];
#pragma unroll
    for (int p = 0; p < 2; p++)
#pragma unroll
        for (int j = 0; j < 4; j++) acc[p][j] = 0ULL;  // {0.0f, 0.0f}

    for (int kb = 0; kb < KDIM; kb += KT) {
        // ---- load 64x32 x-tile and 64x32 W-tile, transposed into smem ----
#pragma unroll
        for (int i = 0; i < 2; i++) {
            int idx = tid + i * 256;       // 0..511
            int row = idx >> 3;            // 0..63
            int c4  = (idx & 7) << 2;      // 0,4,...,28
            float4 v = *(const float4*)&x[(size_t)(t0 + row) * KDIM + kb + c4];
            sm.g.xs[c4 + 0][row] = v.x;
            sm.g.xs[c4 + 1][row] = v.y;
            sm.g.xs[c4 + 2][row] = v.z;
            sm.g.xs[c4 + 3][row] = v.w;
            float4 wv = *(const float4*)&W[(size_t)row * KDIM + kb + c4];
            sm.g.ws[c4 + 0][row] = wv.x;
            sm.g.ws[c4 + 1][row] = wv.y;
            sm.g.ws[c4 + 2][row] = wv.z;
            sm.g.ws[c4 + 3][row] = wv.w;
        }
        __syncthreads();

#pragma unroll
        for (int k = 0; k < KT; k++) {
            u64 x01 = *(const u64*)&sm.g.xs[k][tm];
            u64 x23 = *(const u64*)&sm.g.xs[k][tm + 2];
            float4 wv = *(const float4*)&sm.g.ws[k][tn];
            u64 w0 = packdup(wv.x);
            u64 w1 = packdup(wv.y);
            u64 w2 = packdup(wv.z);
            u64 w3 = packdup(wv.w);
            acc[0][0] = ffma2(x01, w0, acc[0][0]);
            acc[1][0] = ffma2(x23, w0, acc[1][0]);
            acc[0][1] = ffma2(x01, w1, acc[0][1]);
            acc[1][1] = ffma2(x23, w1, acc[1][1]);
            acc[0][2] = ffma2(x01, w2, acc[0][2]);
            acc[1][2] = ffma2(x23, w2, acc[1][2]);
            acc[0][3] = ffma2(x01, w3, acc[0][3]);
            acc[1][3] = ffma2(x23, w3, acc[1][3]);
        }
        __syncthreads();
    }

    // ---- epilogue: logits -> smem, then per-token top-2 + softmax ----
#pragma unroll
    for (int p = 0; p < 2; p++) {
#pragma unroll
        for (int j = 0; j < 4; j++) {
            float lo, hi;
            unpack2(acc[p][j], lo, hi);
            sm.lg[tm + 2 * p + 0][tn + j] = lo;
            sm.lg[tm + 2 * p + 1][tn + j] = hi;
        }
    }
    __syncthreads();

    if (tid < BT) {
        const float* row = sm.lg[tid];
        // first max: strict > keeps lowest index on ties (matches jax top_k)
        float b1 = -3.4e38f; int i1 = 0;
#pragma unroll 8
        for (int e = 0; e < NEXP; e++) {
            float v = row[e];
            if (v > b1) { b1 = v; i1 = e; }
        }
        float b2 = -3.4e38f; int i2 = 0;
#pragma unroll 8
        for (int e = 0; e < NEXP; e++) {
            if (e == i1) continue;
            float v = row[e];
            if (v > b2) { b2 = v; i2 = e; }
        }
        // softmax over {b1, b2}, b1 >= b2
        float s1 = 1.0f / (1.0f + expf(b2 - b1));
        float s2 = 1.0f - s1;

        int t = t0 + tid;
        out[2 * t + 0] = s1;
        out[2 * t + 1] = s2;
        out[2 * T_TOKENS + 2 * t + 0] = (float)i1;
        out[2 * T_TOKENS + 2 * t + 1] = (float)i2;
    }
}

extern "C" void kernel_launch(void* const* d_in, const int* in_sizes, int n_in,
                              void* d_out, int out_size)
{
    const float* x = (const float*)d_in[0];
    const float* W = (const float*)d_in[1];
    float* out = (float*)d_out;
    router_kernel<<<T_TOKENS / BT, THREADS>>>(x, W, out);
}

// round 7
// speedup vs baseline: 2.7266x; 2.7266x over previous
#include <cuda_runtime.h>
#include <cuda_bf16.h>
#include <cstdint>

#define T_TOKENS 16384
#define NEXP     64
#define KDIM     4096
#define BM       128        // tokens per CTA
#define KC       64         // K elems per chunk (128B bf16 row = SW128 atom)
#define NCHUNK   (KDIM / KC)
#define THREADS  256

typedef unsigned long long u64;

// tcgen05 is arch-specific ("a" targets only). The harness's generic sm_103
// pass must never see those instructions.
#if defined(__CUDA_ARCH_FEAT_SM103_ALL) || defined(__CUDA_ARCH_FEAT_SM100_ALL) || defined(__CUDA_ARCH_FEAT_SM101_ALL)
#define HAS_TCGEN05 1
#else
#define HAS_TCGEN05 0
#endif

// bf16 splits of W, packed 4 elems (2x bf16x2) per u64: [split][expert][KDIM/4]
__device__ u64 Wsplit[3][NEXP][KDIM / 4];

// ---------------- portable PTX helpers (plain sm_103-legal) ----------------
__device__ __forceinline__ u64 ffma2(u64 a, u64 b, u64 c) {
    u64 d; asm("fma.rn.f32x2 %0, %1, %2, %3;" : "=l"(d) : "l"(a), "l"(b), "l"(c)); return d;
}
__device__ __forceinline__ u64 pack2f(float lo, float hi) {
    u64 d; asm("mov.b64 %0, {%1, %2};" : "=l"(d) : "f"(lo), "f"(hi)); return d;
}
__device__ __forceinline__ void unpack2f(u64 v, float& lo, float& hi) {
    asm("mov.b64 {%0, %1}, %2;" : "=f"(lo), "=f"(hi) : "l"(v));
}
__device__ __forceinline__ uint32_t cvt_bf2(float lo, float hi) {
    uint32_t r; asm("cvt.rn.bf16x2.f32 %0, %1, %2;" : "=r"(r) : "f"(hi), "f"(lo)); return r;
}
__device__ __forceinline__ u64 bf2_to_f2(uint32_t p) {   // packed bf16x2 -> packed f32x2
    uint32_t lo = p << 16, hi = p & 0xFFFF0000u;
    u64 d; asm("mov.b64 %0, {%1, %2};" : "=l"(d) : "r"(lo), "r"(hi)); return d;
}
__device__ __forceinline__ u64 pk32(uint32_t lo, uint32_t hi) {
    u64 d; asm("mov.b64 %0, {%1, %2};" : "=l"(d) : "r"(lo), "r"(hi)); return d;
}
__device__ __forceinline__ uint32_t smem_u32(const void* p) {
    uint32_t a;
    asm("{ .reg .u64 t; cvta.to.shared.u64 t, %1; cvt.u32.u64 %0, t; }" : "=r"(a) : "l"(p));
    return a;
}
__device__ __forceinline__ void sts64(uint32_t a, u64 v) {
    asm volatile("st.shared.b64 [%0], %1;" :: "r"(a), "l"(v) : "memory");
}

// 3-way bf16 split of two adjacent floats -> three packed bf16x2 words
__device__ __forceinline__ void split3_2(float a, float b,
                                         uint32_t& q0, uint32_t& q1, uint32_t& q2) {
    const u64 M1 = 0xBF800000BF800000ULL;  // {-1.0f, -1.0f}
    u64 xp = pack2f(a, b);
    q0 = cvt_bf2(a, b);
    u64 r1 = ffma2(bf2_to_f2(q0), M1, xp);
    float r1l, r1h; unpack2f(r1, r1l, r1h);
    q1 = cvt_bf2(r1l, r1h);
    u64 r2 = ffma2(bf2_to_f2(q1), M1, r1);
    float r2l, r2h; unpack2f(r2, r2l, r2h);
    q2 = cvt_bf2(r2l, r2h);
}

#define SW128(o) ((o) ^ (((o) >> 3) & 0x70))

#define A_TILE  (BM * 128)      // 16384 B per split
#define B_TILE  (NEXP * 128)    // 8192  B per split
#define BUF_B   (3 * A_TILE + 3 * B_TILE)   // 73728
#define SMEM_DYN (1024 + 2 * BUF_B)         // 148480 (>= fallback's needs too)

#if HAS_TCGEN05
// ---------------- tcgen05-only helpers ----------------
static constexpr uint32_t IDESC =
    (1u << 4) | (1u << 7) | (1u << 10) | ((NEXP / 8) << 17) | ((BM / 16) << 24); // 0x8100490

__device__ __forceinline__ uint32_t elect1() {
    uint32_t p;
    asm volatile("{ .reg .pred p; elect.sync _|p, 0xFFFFFFFF; selp.b32 %0,1,0,p; }" : "=r"(p));
    return p;
}
__device__ __forceinline__ u64 mkdesc(uint32_t addr) {  // SW128, LBO=1, SBO=64, version=1
    const u64 base = (2ULL << 61) | (1ULL << 46) | (64ULL << 32) | (1ULL << 16);
    return base | ((addr >> 4) & 0x3FFF);
}
__device__ __forceinline__ void mma_f16_ss(uint32_t d, u64 ad, u64 bd, uint32_t en) {
    asm volatile(
        "{\n\t.reg .pred p;\n\tsetp.ne.u32 p, %5, 0;\n\t"
        "tcgen05.mma.cta_group::1.kind::f16 [%0], %1, %2, %3, {%4,%4,%4,%4}, p;\n\t}"
        :: "r"(d), "l"(ad), "l"(bd), "r"(IDESC), "r"(0u), "r"(en) : "memory");
}
#define MBAR_INIT(a, n) asm volatile("mbarrier.init.shared.b64 [%0], %1;" :: "r"(a), "r"(n) : "memory")
#define TCG_COMMIT(a) \
    asm volatile("tcgen05.commit.cta_group::1.mbarrier::arrive::one.shared::cluster.b64 [%0];" \
                 :: "r"(a) : "memory")
#define MBAR_WAIT(mbar, par) do {                                                   \
    uint32_t _m = (mbar), _p = (uint32_t)(par), _d;                                 \
    asm volatile("{\n\t.reg .pred p;\n\t"                                           \
        "mbarrier.try_wait.parity.acquire.cta.shared::cta.b64 p, [%1], %2;\n\t"     \
        "selp.b32 %0, 1, 0, p;\n\t}" : "=r"(_d) : "r"(_m), "r"(_p) : "memory");     \
    if (!_d) {                                                                      \
        asm volatile("{\n\t.reg .pred P1;\n\t"                                      \
            "W_%=:\n\t"                                                             \
            "mbarrier.try_wait.parity.acquire.cta.shared::cta.b64 P1, [%0], %1, 0x989680;\n\t" \
            "@P1 bra.uni D_%=;\n\t"                                                 \
            "bra.uni W_%=;\n\t"                                                     \
            "D_%=:\n\t}" :: "r"(_m), "r"(_p) : "memory");                           \
    } } while (0)
#define TCG_ALLOC(sm, n)  asm volatile("tcgen05.alloc.cta_group::1.sync.aligned.shared::cta.b32 [%0], %1;" :: "r"(sm), "r"(n) : "memory")
#define TCG_RELINQ()      asm volatile("tcgen05.relinquish_alloc_permit.cta_group::1.sync.aligned;")
#define TCG_DEALLOC(t, n) asm volatile("tcgen05.dealloc.cta_group::1.sync.aligned.b32 %0, %1;" :: "r"(t), "r"(n))
#define TCG_FENCE_AFTER() asm volatile("tcgen05.fence::after_thread_sync;" ::: "memory")
#define TCG_WAIT_LD()     asm volatile("tcgen05.wait::ld.sync.aligned;" ::: "memory")

#define LDTM32(r, addr) \
    asm volatile("tcgen05.ld.sync.aligned.32x32b.x32.b32 " \
        "{%0,%1,%2,%3,%4,%5,%6,%7,%8,%9,%10,%11,%12,%13,%14,%15," \
        "%16,%17,%18,%19,%20,%21,%22,%23,%24,%25,%26,%27,%28,%29,%30,%31}, [%32];" \
        : "=r"((r)[0]),"=r"((r)[1]),"=r"((r)[2]),"=r"((r)[3]),"=r"((r)[4]),"=r"((r)[5]), \
          "=r"((r)[6]),"=r"((r)[7]),"=r"((r)[8]),"=r"((r)[9]),"=r"((r)[10]),"=r"((r)[11]), \
          "=r"((r)[12]),"=r"((r)[13]),"=r"((r)[14]),"=r"((r)[15]),"=r"((r)[16]),"=r"((r)[17]), \
          "=r"((r)[18]),"=r"((r)[19]),"=r"((r)[20]),"=r"((r)[21]),"=r"((r)[22]),"=r"((r)[23]), \
          "=r"((r)[24]),"=r"((r)[25]),"=r"((r)[26]),"=r"((r)[27]),"=r"((r)[28]),"=r"((r)[29]), \
          "=r"((r)[30]),"=r"((r)[31]) : "r"(addr))
#endif  // HAS_TCGEN05

// ---------------- W split precompute (no-op on generic pass) ----------------
__global__ void wsplit_kernel(const float* __restrict__ W) {
#if HAS_TCGEN05
    int idx = blockIdx.x * blockDim.x + threadIdx.x;
    if (idx >= NEXP * (KDIM / 4)) return;
    int row = idx >> 10;
    int j   = idx & 1023;
    const float* p = W + (size_t)row * KDIM + j * 4;
    uint32_t a0, a1, a2, b0, b1, b2;
    split3_2(p[0], p[1], a0, a1, a2);
    split3_2(p[2], p[3], b0, b1, b2);
    Wsplit[0][row][j] = pk32(a0, b0);
    Wsplit[1][row][j] = pk32(a1, b1);
    Wsplit[2][row][j] = pk32(a2, b2);
#endif
}

#if HAS_TCGEN05
__device__ __forceinline__ void ldg_chunk(const float* __restrict__ x, int t0, int c, int tid,
                                          float4 xr[8], u64 wr[12]) {
    const float* xp = x + (size_t)t0 * KDIM + c * KC;
#pragma unroll
    for (int i = 0; i < 8; i++) {
        int idx = tid + i * 256;
        int row = idx >> 4, c4 = idx & 15;
        xr[i] = *(const float4*)(xp + (size_t)row * KDIM + c4 * 4);
    }
#pragma unroll
    for (int s = 0; s < 3; s++)
#pragma unroll
        for (int i = 0; i < 4; i++) {
            int idx = tid + i * 256;
            int row = idx >> 4, j = idx & 15;
            wr[s * 4 + i] = Wsplit[s][row][c * 16 + j];
        }
}
#endif

// ---------------- main fused kernel: one symbol, two bodies ----------------
__global__ __launch_bounds__(THREADS, 1)
void router_mma(const float* __restrict__ x,
                const float* __restrict__ W,
                float* __restrict__ out)
{
#if HAS_TCGEN05
    // ============== tcgen05 path (arch-specific target) ==============
    extern __shared__ char dsm[];
    __shared__ uint32_t s_tmem;
    __shared__ __align__(8) u64 s_mbar[2];

    const int tid = threadIdx.x;
    const int wid = tid >> 5, lid = tid & 31;
    const int t0 = blockIdx.x * BM;

    const uint32_t dbase = (smem_u32(dsm) + 1023u) & ~1023u;

    if (wid == 0) TCG_ALLOC(smem_u32(&s_tmem), 128);
    if (tid == 0) { MBAR_INIT(smem_u32(&s_mbar[0]), 1); MBAR_INIT(smem_u32(&s_mbar[1]), 1); }
    __syncthreads();
    const uint32_t tmem = s_tmem;
    if (wid == 0) TCG_RELINQ();
    const uint32_t mb0 = smem_u32(&s_mbar[0]);
    const uint32_t mb1 = smem_u32(&s_mbar[1]);
    int ph0 = 0, ph1 = 0;

    float4 xr[8]; u64 wr[12];
    ldg_chunk(x, t0, 0, tid, xr, wr);

#pragma unroll 1
    for (int c = 0; c < NCHUNK; ++c) {
        float4 xn[8]; u64 wn[12];
        if (c + 1 < NCHUNK) ldg_chunk(x, t0, c + 1, tid, xn, wn);

        const int buf = c & 1;
        if (c >= 2) {
            if (buf == 0) { MBAR_WAIT(mb0, ph0); ph0 ^= 1; }
            else          { MBAR_WAIT(mb1, ph1); ph1 ^= 1; }
        }

        const uint32_t aB = dbase + (uint32_t)buf * BUF_B;
        const uint32_t bB = aB + 3 * A_TILE;

#pragma unroll
        for (int i = 0; i < 8; i++) {
            int idx = tid + i * 256;
            int row = idx >> 4, c4 = idx & 15;
            uint32_t q0a, q1a, q2a, q0b, q1b, q2b;
            split3_2(xr[i].x, xr[i].y, q0a, q1a, q2a);
            split3_2(xr[i].z, xr[i].w, q0b, q1b, q2b);
            uint32_t off = SW128((uint32_t)(row * 128 + c4 * 8));
            sts64(aB + 0 * A_TILE + off, pk32(q0a, q0b));
            sts64(aB + 1 * A_TILE + off, pk32(q1a, q1b));
            sts64(aB + 2 * A_TILE + off, pk32(q2a, q2b));
        }
#pragma unroll
        for (int s = 0; s < 3; s++)
#pragma unroll
            for (int i = 0; i < 4; i++) {
                int idx = tid + i * 256;
                int row = idx >> 4, j = idx & 15;
                uint32_t off = SW128((uint32_t)(row * 128 + j * 8));
                sts64(bB + s * B_TILE + off, wr[s * 4 + i]);
            }

        asm volatile("fence.proxy.async.shared::cta;" ::: "memory");
        __syncthreads();

        if (wid == 0 && elect1()) {
            u64 ad0 = mkdesc(aB), ad1 = mkdesc(aB + A_TILE), ad2 = mkdesc(aB + 2 * A_TILE);
            u64 bd0 = mkdesc(bB), bd1 = mkdesc(bB + B_TILE), bd2 = mkdesc(bB + 2 * B_TILE);
#pragma unroll
            for (int ks = 0; ks < 4; ks++) {
                u64 o = 2 * ks;
                mma_f16_ss(tmem, ad0 + o, bd0 + o, (c == 0 && ks == 0) ? 0u : 1u);
                mma_f16_ss(tmem, ad0 + o, bd1 + o, 1u);
                mma_f16_ss(tmem, ad1 + o, bd0 + o, 1u);
                mma_f16_ss(tmem, ad0 + o, bd2 + o, 1u);
                mma_f16_ss(tmem, ad1 + o, bd1 + o, 1u);
                mma_f16_ss(tmem, ad2 + o, bd0 + o, 1u);
            }
            TCG_COMMIT(buf == 0 ? mb0 : mb1);
        }

        if (c + 1 < NCHUNK) {
#pragma unroll
            for (int i = 0; i < 8; i++) xr[i] = xn[i];
#pragma unroll
            for (int i = 0; i < 12; i++) wr[i] = wn[i];
        }
    }

    MBAR_WAIT(mb0, ph0);
    MBAR_WAIT(mb1, ph1);
    TCG_FENCE_AFTER();

    if (wid < 4) {
        uint32_t dr[64];
        LDTM32(dr, tmem);
        LDTM32(dr + 32, tmem + 32);
        TCG_WAIT_LD();

        float fv[NEXP];
#pragma unroll
        for (int e = 0; e < NEXP; e++) fv[e] = __uint_as_float(dr[e]);

        float b1 = -3.4e38f; int i1 = 0;
#pragma unroll
        for (int e = 0; e < NEXP; e++) if (fv[e] > b1) { b1 = fv[e]; i1 = e; }
        float b2 = -3.4e38f; int i2 = 0;
#pragma unroll
        for (int e = 0; e < NEXP; e++) if (e != i1 && fv[e] > b2) { b2 = fv[e]; i2 = e; }

        float s1 = 1.0f / (1.0f + expf(b2 - b1));
        float s2 = 1.0f - s1;

        int t = t0 + wid * 32 + lid;
        out[2 * t + 0] = s1;
        out[2 * t + 1] = s2;
        out[2 * T_TOKENS + 2 * t + 0] = (float)i1;
        out[2 * T_TOKENS + 2 * t + 1] = (float)i2;
    }

    __syncthreads();
    if (wid == 0) TCG_DEALLOC(tmem, 128);

#else
    // ============== fallback: proven FFMA f32x2 path (generic sm_103) ==============
    extern __shared__ char dsm[];
    struct SmG { float xs[32][64 + 2]; float ws[32][64 + 4]; };
    typedef float SmL[64][64 + 1];
    SmG* g  = (SmG*)dsm;
    SmL* lg = (SmL*)dsm;

    const int tid = threadIdx.x;
    const int tm = (tid >> 4) << 2;
    const int tn = (tid & 15) << 2;

#pragma unroll 1
    for (int h = 0; h < 2; h++) {
        const int t0 = blockIdx.x * BM + h * 64;

        u64 acc[2][4];
#pragma unroll
        for (int p = 0; p < 2; p++)
#pragma unroll
            for (int j = 0; j < 4; j++) acc[p][j] = 0ULL;

        __syncthreads();   // smem reuse across halves / epilogue

#pragma unroll 1
        for (int kb = 0; kb < KDIM; kb += 32) {
#pragma unroll
            for (int i = 0; i < 2; i++) {
                int idx = tid + i * 256;
                int row = idx >> 3;
                int c4  = (idx & 7) << 2;
                float4 v = *(const float4*)&x[(size_t)(t0 + row) * KDIM + kb + c4];
                g->xs[c4 + 0][row] = v.x;
                g->xs[c4 + 1][row] = v.y;
                g->xs[c4 + 2][row] = v.z;
                g->xs[c4 + 3][row] = v.w;
                float4 wv = *(const float4*)&W[(size_t)row * KDIM + kb + c4];
                g->ws[c4 + 0][row] = wv.x;
                g->ws[c4 + 1][row] = wv.y;
                g->ws[c4 + 2][row] = wv.z;
                g->ws[c4 + 3][row] = wv.w;
            }
            __syncthreads();

#pragma unroll
            for (int k = 0; k < 32; k++) {
                u64 x01 = *(const u64*)&g->xs[k][tm];
                u64 x23 = *(const u64*)&g->xs[k][tm + 2];
                float4 wv = *(const float4*)&g->ws[k][tn];
                u64 w0 = pack2f(wv.x, wv.x);
                u64 w1 = pack2f(wv.y, wv.y);
                u64 w2 = pack2f(wv.z, wv.z);
                u64 w3 = pack2f(wv.w, wv.w);
                acc[0][0] = ffma2(x01, w0, acc[0][0]);
                acc[1][0] = ffma2(x23, w0, acc[1][0]);
                acc[0][1] = ffma2(x01, w1, acc[0][1]);
                acc[1][1] = ffma2(x23, w1, acc[1][1]);
                acc[0][2] = ffma2(x01, w2, acc[0][2]);
                acc[1][2] = ffma2(x23, w2, acc[1][2]);
                acc[0][3] = ffma2(x01, w3, acc[0][3]);
                acc[1][3] = ffma2(x23, w3, acc[1][3]);
            }
            __syncthreads();
        }

#pragma unroll
        for (int p = 0; p < 2; p++)
#pragma unroll
            for (int j = 0; j < 4; j++) {
                float lo, hi;
                unpack2f(acc[p][j], lo, hi);
                (*lg)[tm + 2 * p + 0][tn + j] = lo;
                (*lg)[tm + 2 * p + 1][tn + j] = hi;
            }
        __syncthreads();

        if (tid < 64) {
            const float* row = (*lg)[tid];
            float b1 = -3.4e38f; int i1 = 0;
#pragma unroll 8
            for (int e = 0; e < NEXP; e++) {
                float v = row[e];
                if (v > b1) { b1 = v; i1 = e; }
            }
            float b2 = -3.4e38f; int i2 = 0;
#pragma unroll 8
            for (int e = 0; e < NEXP; e++) {
                if (e == i1) continue;
                float v = row[e];
                if (v > b2) { b2 = v; i2 = e; }
            }
            float s1 = 1.0f / (1.0f + expf(b2 - b1));
            float s2 = 1.0f - s1;

            int t = t0 + tid;
            out[2 * t + 0] = s1;
            out[2 * t + 1] = s2;
            out[2 * T_TOKENS + 2 * t + 0] = (float)i1;
            out[2 * T_TOKENS + 2 * t + 1] = (float)i2;
        }
    }
#endif
}

extern "C" void kernel_launch(void* const* d_in, const int* in_sizes, int n_in,
                              void* d_out, int out_size) {
    const float* x = (const float*)d_in[0];
    const float* W = (const float*)d_in[1];
    float* out = (float*)d_out;

    cudaFuncSetAttribute(router_mma, cudaFuncAttributeMaxDynamicSharedMemorySize, SMEM_DYN);

    wsplit_kernel<<<(NEXP * (KDIM / 4) + 255) / 256, 256>>>(W);
    router_mma<<<T_TOKENS / BM, THREADS, SMEM_DYN>>>(x, W, out);
}